// round 2
// baseline (speedup 1.0000x reference)
#include <cuda_runtime.h>

// reaction_diffusion: out = tanh(in @ Lr^T + br) + in @ Ld^T + bd + in
// Lr = diag(colsum(Wr)) - Wr, Wr[ei,ej] += wr   (reaction)
// Ld = diag(colsum(Wd)) - Wd, Wd[ej,ei] += wd   (diffusion)
//
// Edge-flow form (no dense matrices):
//   reaction[b,n] = in[b,n]*cs_r[n] - sum_{k: ei_k=n} wr_k * in[b, ej_k] + br[n]
//     cs_r[n] = sum_{k: ej_k=n} wr_k
//   => per edge k: t = wr_k * in[ej];  r[ej] += t;  r[ei] -= t;
//   diffusion mirror: u = wd_k * in[ei];  d[ei] += u;  d[ej] -= u;

#define N_NODES 207
#define N_EDGES 1722
#define BATCH   64

__global__ __launch_bounds__(256)
void rd_kernel(const float* __restrict__ in,
               const float* __restrict__ wr,
               const float* __restrict__ wd,
               const float* __restrict__ br,
               const float* __restrict__ bd,
               const int*   __restrict__ ei,
               const int*   __restrict__ ej,
               float* __restrict__ out) {
    __shared__ float s_in[N_NODES];
    __shared__ float s_r[N_NODES];
    __shared__ float s_d[N_NODES];

    const int b = blockIdx.x;
    const int t = threadIdx.x;

    // load this batch row + zero accumulators
    for (int n = t; n < N_NODES; n += blockDim.x) {
        s_in[n] = in[b * N_NODES + n];
        s_r[n]  = 0.0f;
        s_d[n]  = 0.0f;
    }
    __syncthreads();

    // edge-parallel accumulation (smem atomics)
    for (int k = t; k < N_EDGES; k += blockDim.x) {
        const int i = ei[k];
        const int j = ej[k];
        const float vr = wr[k] * s_in[j];   // reaction flow
        atomicAdd(&s_r[j],  vr);
        atomicAdd(&s_r[i], -vr);
        const float vd = wd[k] * s_in[i];   // diffusion flow
        atomicAdd(&s_d[i],  vd);
        atomicAdd(&s_d[j], -vd);
    }
    __syncthreads();

    // finalize: tanh(reaction + br) + diffusion + bd + in
    for (int n = t; n < N_NODES; n += blockDim.x) {
        const float x = s_in[n];
        out[b * N_NODES + n] = tanhf(s_r[n] + br[n]) + s_d[n] + bd[n] + x;
    }
}

extern "C" void kernel_launch(void* const* d_in, const int* in_sizes, int n_in,
                              void* d_out, int out_size) {
    const float* in_ = (const float*)d_in[0];
    const float* wr  = (const float*)d_in[1];
    const float* wd  = (const float*)d_in[2];
    const float* br  = (const float*)d_in[3];
    const float* bd  = (const float*)d_in[4];
    const int*   ei  = (const int*)d_in[5];
    const int*   ej  = (const int*)d_in[6];
    float* out = (float*)d_out;

    rd_kernel<<<BATCH, 256>>>(in_, wr, wd, br, bd, ei, ej, out);
}